// round 4
// baseline (speedup 1.0000x reference)
#include <cuda_runtime.h>

#define NSQ     64
#define PSTRIDE 20
#define TPB     128
#define PPT     4
#define EPSF    1e-6f
#define TRUNCF  0.1f

__device__ float g_params[NSQ * PSTRIDE];

// ---------------------------------------------------------------------------
// Per-superquadric parameter precompute (64 threads, one launch).
// Layout per SQ (stride 20 floats):
//  [0..8]  M = R^T row-major (Xc = M * (p - t))
//  [9..11] t
//  [12..14] 1/sx, 1/sy, 1/sz
//  [15] 2/e1   [16] 2/e2   [17] e2/e1   [18] -e1/2   [19] pad
// ---------------------------------------------------------------------------
__global__ void sq_precompute(const float* __restrict__ raw_scale,
                              const float* __restrict__ raw_exps,
                              const float* __restrict__ raw_rot,
                              const float* __restrict__ trans) {
    int j = threadIdx.x;
    if (j >= NSQ) return;

    float sx = expf(raw_scale[3 * j + 0]);
    float sy = expf(raw_scale[3 * j + 1]);
    float sz = expf(raw_scale[3 * j + 2]);

    float e1 = 0.1f + 1.8f / (1.0f + expf(-raw_exps[2 * j + 0]));
    float e2 = 0.1f + 1.8f / (1.0f + expf(-raw_exps[2 * j + 1]));

    float qw = raw_rot[4 * j + 0], qx = raw_rot[4 * j + 1];
    float qy = raw_rot[4 * j + 2], qz = raw_rot[4 * j + 3];
    float qn = sqrtf(qw * qw + qx * qx + qy * qy + qz * qz);
    qw /= qn; qx /= qn; qy /= qn; qz /= qn;

    float R00 = 1.f - 2.f * (qy * qy + qz * qz);
    float R01 = 2.f * (qx * qy - qw * qz);
    float R02 = 2.f * (qx * qz + qw * qy);
    float R10 = 2.f * (qx * qy + qw * qz);
    float R11 = 1.f - 2.f * (qx * qx + qz * qz);
    float R12 = 2.f * (qy * qz - qw * qx);
    float R20 = 2.f * (qx * qz - qw * qy);
    float R21 = 2.f * (qy * qz + qw * qx);
    float R22 = 1.f - 2.f * (qx * qx + qy * qy);

    float* p = &g_params[j * PSTRIDE];
    // M = R^T: row i of M = column i of R
    p[0] = R00; p[1] = R10; p[2] = R20;
    p[3] = R01; p[4] = R11; p[5] = R21;
    p[6] = R02; p[7] = R12; p[8] = R22;
    p[9]  = trans[3 * j + 0];
    p[10] = trans[3 * j + 1];
    p[11] = trans[3 * j + 2];
    p[12] = 1.f / sx; p[13] = 1.f / sy; p[14] = 1.f / sz;
    p[15] = 2.f / e1; p[16] = 2.f / e2;
    p[17] = e2 / e1;  p[18] = -0.5f * e1;
    p[19] = 0.f;
}

// a > 0 always at call sites; fast MUFU path.
__device__ __forceinline__ float powlog(float lg, float e) { return exp2f(e * lg); }

// ---------------------------------------------------------------------------
// Main kernel: phase 1 = SDF min-scan over 64 SQs (SDF only), phase 2 =
// analytic gradient (autodiff-equivalent) of the winning SQ per point.
// ---------------------------------------------------------------------------
__global__ void __launch_bounds__(TPB)
sq_main(const float* __restrict__ points, float* __restrict__ out, int P) {
    __shared__ float sp[NSQ * PSTRIDE];
    for (int i = threadIdx.x; i < NSQ * PSTRIDE; i += TPB) sp[i] = g_params[i];
    __syncthreads();

    const int base = blockIdx.x * (TPB * PPT) + threadIdx.x;

    float px[PPT], py[PPT], pz[PPT], best[PPT];
    int bidx[PPT];
#pragma unroll
    for (int k = 0; k < PPT; k++) {
        int i = base + k * TPB;
        int ii = (i < P) ? i : 0;
        px[k] = points[3 * ii + 0];
        py[k] = points[3 * ii + 1];
        pz[k] = points[3 * ii + 2];
        best[k] = 3.0e38f;
        bidx[k] = 0;
    }

    // ---- Phase 1: SDF only, first-strict-min over SQ index ----
#pragma unroll 1
    for (int j = 0; j < NSQ; j++) {
        const float* q = &sp[j * PSTRIDE];
        float M00 = q[0], M01 = q[1], M02 = q[2];
        float M10 = q[3], M11 = q[4], M12 = q[5];
        float M20 = q[6], M21 = q[7], M22 = q[8];
        float tx = q[9], ty = q[10], tz = q[11];
        float isx = q[12], isy = q[13], isz = q[14];
        float ie1 = q[15], ie2 = q[16], e21 = q[17], nh1 = q[18];

#pragma unroll
        for (int k = 0; k < PPT; k++) {
            float ux = px[k] - tx, uy = py[k] - ty, uz = pz[k] - tz;
            float c0 = fmaf(M02, uz, fmaf(M01, uy, M00 * ux));
            float c1 = fmaf(M12, uz, fmaf(M11, uy, M10 * ux));
            float c2 = fmaf(M22, uz, fmaf(M21, uy, M20 * ux));
            float xa = fmaxf(fabsf(c0), EPSF);
            float ya = fmaxf(fabsf(c1), EPSF);
            float za = fmaxf(fabsf(c2), EPSF);
            float r2 = fmaf(xa, xa, fmaf(ya, ya, za * za));
            float r0 = sqrtf(r2);
            // t1 = ((x/sx)^2)^(1/e2) = exp2((2/e2) * log2(|x|/sx))
            float t1 = powlog(__log2f(xa * isx), ie2);
            float t2 = powlog(__log2f(ya * isy), ie2);
            float t3 = powlog(__log2f(za * isz), ie1);
            float h = t1 + t2 + EPSF;
            float hp = powlog(__log2f(h), e21);
            float g = hp + t3;
            float f = powlog(__log2f(g), nh1);
            float s = r0 * (1.0f - f);
            s = fminf(fmaxf(s, -TRUNCF), TRUNCF);
            bool lt = s < best[k];
            best[k] = lt ? s : best[k];
            bidx[k] = lt ? j : bidx[k];
        }
    }

    // ---- Phase 2: analytic gradient for the winning SQ per point ----
#pragma unroll 1
    for (int k = 0; k < PPT; k++) {
        int i = base + k * TPB;
        if (i >= P) continue;
        const float* q = &sp[bidx[k] * PSTRIDE];
        float M00 = q[0], M01 = q[1], M02 = q[2];
        float M10 = q[3], M11 = q[4], M12 = q[5];
        float M20 = q[6], M21 = q[7], M22 = q[8];
        float tx = q[9], ty = q[10], tz = q[11];
        float isx = q[12], isy = q[13], isz = q[14];
        float ie1 = q[15], ie2 = q[16], e21 = q[17], nh1 = q[18];

        float ux = px[k] - tx, uy = py[k] - ty, uz = pz[k] - tz;
        float c0 = fmaf(M02, uz, fmaf(M01, uy, M00 * ux));
        float c1 = fmaf(M12, uz, fmaf(M11, uy, M10 * ux));
        float c2 = fmaf(M22, uz, fmaf(M21, uy, M20 * ux));
        float xa = fmaxf(fabsf(c0), EPSF);
        float ya = fmaxf(fabsf(c1), EPSF);
        float za = fmaxf(fabsf(c2), EPSF);
        // signed clamped coords: sign = (Xc>0)*2-1 (matches reference at 0)
        float x = (c0 > 0.f) ? xa : -xa;
        float y = (c1 > 0.f) ? ya : -ya;
        float z = (c2 > 0.f) ? za : -za;
        float r2 = fmaf(xa, xa, fmaf(ya, ya, za * za));
        float r0 = sqrtf(r2);
        float t1 = powlog(__log2f(xa * isx), ie2);
        float t2 = powlog(__log2f(ya * isy), ie2);
        float t3 = powlog(__log2f(za * isz), ie1);
        float h = t1 + t2 + EPSF;
        float hp = powlog(__log2f(h), e21);
        float g = hp + t3;
        float f = powlog(__log2f(g), nh1);

        float inv_r0 = 1.0f / r0;
        float omf = 1.0f - f;
        float com = r0 * (f / g);      // r0 * f / g
        float hh  = hp / h;            // h^(e2/e1 - 1)

        // d sdf / d X_i  (derivation: dsdf/dX = (X/r0)(1-f) + r0*(f/g)*dg/dX*(e1/2),
        //  dg/dx = (2/e1)(hp/h)(t1/x), dg/dz = (2/e1)(t3/z) -> (e1/2) cancels)
        // eps-clamp active -> zero gradient through max(|Xc|, eps)
        float gx = (fabsf(c0) > EPSF) ? fmaf(x * inv_r0, omf, com * hh * (t1 / x)) : 0.0f;
        float gy = (fabsf(c1) > EPSF) ? fmaf(y * inv_r0, omf, com * hh * (t2 / y)) : 0.0f;
        float gz = (fabsf(c2) > EPSF) ? fmaf(z * inv_r0, omf, com * (t3 / z)) : 0.0f;

        // back to world frame: grad_p = M^T * gX (M = R^T, so grad_p = R * gX)
        float gpx = fmaf(M20, gz, fmaf(M10, gy, M00 * gx));
        float gpy = fmaf(M21, gz, fmaf(M11, gy, M01 * gx));
        float gpz = fmaf(M22, gz, fmaf(M12, gy, M02 * gx));

        float nn = sqrtf(fmaf(gpx, gpx, fmaf(gpy, gpy, gpz * gpz)));
        float dn = fmaxf(nn, 1e-12f);

        out[i] = best[k];
        float* on = out + P;
        on[3 * i + 0] = gpx / dn;
        on[3 * i + 1] = gpy / dn;
        on[3 * i + 2] = gpz / dn;
    }
}

extern "C" void kernel_launch(void* const* d_in, const int* in_sizes, int n_in,
                              void* d_out, int out_size) {
    const float* raw_scale = (const float*)d_in[0];
    const float* raw_exps  = (const float*)d_in[1];
    const float* raw_rot   = (const float*)d_in[2];
    const float* trans     = (const float*)d_in[3];
    const float* points    = (const float*)d_in[4];
    int P = in_sizes[4] / 3;

    sq_precompute<<<1, 64>>>(raw_scale, raw_exps, raw_rot, trans);

    int total_threads = (P + PPT - 1) / PPT;
    int blocks = (total_threads + TPB - 1) / TPB;
    sq_main<<<blocks, TPB>>>(points, (float*)d_out, P);
}

// round 6
// speedup vs baseline: 1.1456x; 1.1456x over previous
#include <cuda_runtime.h>

#define NSQ     64
#define PSTRIDE 20
#define TPB     128
#define PPT     2
#define EPSF    1e-6f
#define TRUNCF  0.1f

__device__ float g_params[NSQ * PSTRIDE];

// ---------------------------------------------------------------------------
// Per-superquadric parameter precompute (64 threads, one launch).
// Layout per SQ (stride 20 floats):
//  [0..8]  M = R^T row-major (Xc = M * (p - t))
//  [9..11] t
//  [12..14] 1/sx, 1/sy, 1/sz
//  [15] 2/e1   [16] 2/e2   [17] e2/e1   [18] -e1/2   [19] pad
// ---------------------------------------------------------------------------
__global__ void sq_precompute(const float* __restrict__ raw_scale,
                              const float* __restrict__ raw_exps,
                              const float* __restrict__ raw_rot,
                              const float* __restrict__ trans) {
    int j = threadIdx.x;
    if (j >= NSQ) return;

    float sx = expf(raw_scale[3 * j + 0]);
    float sy = expf(raw_scale[3 * j + 1]);
    float sz = expf(raw_scale[3 * j + 2]);

    float e1 = 0.1f + 1.8f / (1.0f + expf(-raw_exps[2 * j + 0]));
    float e2 = 0.1f + 1.8f / (1.0f + expf(-raw_exps[2 * j + 1]));

    float qw = raw_rot[4 * j + 0], qx = raw_rot[4 * j + 1];
    float qy = raw_rot[4 * j + 2], qz = raw_rot[4 * j + 3];
    float qn = sqrtf(qw * qw + qx * qx + qy * qy + qz * qz);
    qw /= qn; qx /= qn; qy /= qn; qz /= qn;

    float R00 = 1.f - 2.f * (qy * qy + qz * qz);
    float R01 = 2.f * (qx * qy - qw * qz);
    float R02 = 2.f * (qx * qz + qw * qy);
    float R10 = 2.f * (qx * qy + qw * qz);
    float R11 = 1.f - 2.f * (qx * qx + qz * qz);
    float R12 = 2.f * (qy * qz - qw * qx);
    float R20 = 2.f * (qx * qz - qw * qy);
    float R21 = 2.f * (qy * qz + qw * qx);
    float R22 = 1.f - 2.f * (qx * qx + qy * qy);

    float* p = &g_params[j * PSTRIDE];
    // M = R^T: row i of M = column i of R
    p[0] = R00; p[1] = R10; p[2] = R20;
    p[3] = R01; p[4] = R11; p[5] = R21;
    p[6] = R02; p[7] = R12; p[8] = R22;
    p[9]  = trans[3 * j + 0];
    p[10] = trans[3 * j + 1];
    p[11] = trans[3 * j + 2];
    p[12] = 1.f / sx; p[13] = 1.f / sy; p[14] = 1.f / sz;
    p[15] = 2.f / e1; p[16] = 2.f / e2;
    p[17] = e2 / e1;  p[18] = -0.5f * e1;
    p[19] = 0.f;
}

// a > 0 always at call sites; fast MUFU path.
__device__ __forceinline__ float powlog(float lg, float e) { return exp2f(e * lg); }

// ---------------------------------------------------------------------------
// Main kernel: phase 1 = SDF min-scan over 64 SQs (SDF only), phase 2 =
// analytic gradient (autodiff-equivalent) of the winning SQ per point.
// ---------------------------------------------------------------------------
__global__ void __launch_bounds__(TPB)
sq_main(const float* __restrict__ points, float* __restrict__ out, int P) {
    __shared__ float sp[NSQ * PSTRIDE];
    for (int i = threadIdx.x; i < NSQ * PSTRIDE; i += TPB) sp[i] = g_params[i];
    __syncthreads();

    const int base = blockIdx.x * (TPB * PPT) + threadIdx.x;

    float px[PPT], py[PPT], pz[PPT], best[PPT];
    int bidx[PPT];
#pragma unroll
    for (int k = 0; k < PPT; k++) {
        int i = base + k * TPB;
        int ii = (i < P) ? i : 0;
        px[k] = points[3 * ii + 0];
        py[k] = points[3 * ii + 1];
        pz[k] = points[3 * ii + 2];
        best[k] = 3.0e38f;
        bidx[k] = 0;
    }

    // ---- Phase 1: SDF only, first-strict-min over SQ index ----
#pragma unroll 1
    for (int j = 0; j < NSQ; j++) {
        const float* q = &sp[j * PSTRIDE];
        float M00 = q[0], M01 = q[1], M02 = q[2];
        float M10 = q[3], M11 = q[4], M12 = q[5];
        float M20 = q[6], M21 = q[7], M22 = q[8];
        float tx = q[9], ty = q[10], tz = q[11];
        float isx = q[12], isy = q[13], isz = q[14];
        float ie1 = q[15], ie2 = q[16], e21 = q[17], nh1 = q[18];

#pragma unroll
        for (int k = 0; k < PPT; k++) {
            float ux = px[k] - tx, uy = py[k] - ty, uz = pz[k] - tz;
            float c0 = fmaf(M02, uz, fmaf(M01, uy, M00 * ux));
            float c1 = fmaf(M12, uz, fmaf(M11, uy, M10 * ux));
            float c2 = fmaf(M22, uz, fmaf(M21, uy, M20 * ux));
            float xa = fmaxf(fabsf(c0), EPSF);
            float ya = fmaxf(fabsf(c1), EPSF);
            float za = fmaxf(fabsf(c2), EPSF);
            float r2 = fmaf(xa, xa, fmaf(ya, ya, za * za));
            float r0 = sqrtf(r2);
            // t1 = ((x/sx)^2)^(1/e2) = exp2((2/e2) * log2(|x|/sx))
            float t1 = powlog(__log2f(xa * isx), ie2);
            float t2 = powlog(__log2f(ya * isy), ie2);
            float t3 = powlog(__log2f(za * isz), ie1);
            float h = t1 + t2 + EPSF;
            float hp = powlog(__log2f(h), e21);
            float g = hp + t3;
            float f = powlog(__log2f(g), nh1);
            float s = r0 * (1.0f - f);
            s = fminf(fmaxf(s, -TRUNCF), TRUNCF);
            bool lt = s < best[k];
            best[k] = lt ? s : best[k];
            bidx[k] = lt ? j : bidx[k];
        }
    }

    // ---- Phase 2: analytic gradient for the winning SQ per point ----
#pragma unroll 1
    for (int k = 0; k < PPT; k++) {
        int i = base + k * TPB;
        if (i >= P) continue;
        const float* q = &sp[bidx[k] * PSTRIDE];
        float M00 = q[0], M01 = q[1], M02 = q[2];
        float M10 = q[3], M11 = q[4], M12 = q[5];
        float M20 = q[6], M21 = q[7], M22 = q[8];
        float tx = q[9], ty = q[10], tz = q[11];
        float isx = q[12], isy = q[13], isz = q[14];
        float ie1 = q[15], ie2 = q[16], e21 = q[17], nh1 = q[18];

        float ux = px[k] - tx, uy = py[k] - ty, uz = pz[k] - tz;
        float c0 = fmaf(M02, uz, fmaf(M01, uy, M00 * ux));
        float c1 = fmaf(M12, uz, fmaf(M11, uy, M10 * ux));
        float c2 = fmaf(M22, uz, fmaf(M21, uy, M20 * ux));
        float xa = fmaxf(fabsf(c0), EPSF);
        float ya = fmaxf(fabsf(c1), EPSF);
        float za = fmaxf(fabsf(c2), EPSF);
        // signed clamped coords: sign = (Xc>0)*2-1 (matches reference at 0)
        float x = (c0 > 0.f) ? xa : -xa;
        float y = (c1 > 0.f) ? ya : -ya;
        float z = (c2 > 0.f) ? za : -za;
        float r2 = fmaf(xa, xa, fmaf(ya, ya, za * za));
        float r0 = sqrtf(r2);
        float t1 = powlog(__log2f(xa * isx), ie2);
        float t2 = powlog(__log2f(ya * isy), ie2);
        float t3 = powlog(__log2f(za * isz), ie1);
        float h = t1 + t2 + EPSF;
        float hp = powlog(__log2f(h), e21);
        float g = hp + t3;
        float f = powlog(__log2f(g), nh1);

        float inv_r0 = 1.0f / r0;
        float omf = 1.0f - f;
        float com = r0 * (f / g);      // r0 * f / g
        float hh  = hp / h;            // h^(e2/e1 - 1)

        // d sdf / d X_i  (derivation: dsdf/dX = (X/r0)(1-f) + r0*(f/g)*dg/dX*(e1/2),
        //  dg/dx = (2/e1)(hp/h)(t1/x), dg/dz = (2/e1)(t3/z) -> (e1/2) cancels)
        // eps-clamp active -> zero gradient through max(|Xc|, eps)
        float gx = (fabsf(c0) > EPSF) ? fmaf(x * inv_r0, omf, com * hh * (t1 / x)) : 0.0f;
        float gy = (fabsf(c1) > EPSF) ? fmaf(y * inv_r0, omf, com * hh * (t2 / y)) : 0.0f;
        float gz = (fabsf(c2) > EPSF) ? fmaf(z * inv_r0, omf, com * (t3 / z)) : 0.0f;

        // back to world frame: grad_p = M^T * gX (M = R^T, so grad_p = R * gX)
        float gpx = fmaf(M20, gz, fmaf(M10, gy, M00 * gx));
        float gpy = fmaf(M21, gz, fmaf(M11, gy, M01 * gx));
        float gpz = fmaf(M22, gz, fmaf(M12, gy, M02 * gx));

        float nn = sqrtf(fmaf(gpx, gpx, fmaf(gpy, gpy, gpz * gpz)));
        float dn = fmaxf(nn, 1e-12f);

        out[i] = best[k];
        float* on = out + P;
        on[3 * i + 0] = gpx / dn;
        on[3 * i + 1] = gpy / dn;
        on[3 * i + 2] = gpz / dn;
    }
}

extern "C" void kernel_launch(void* const* d_in, const int* in_sizes, int n_in,
                              void* d_out, int out_size) {
    const float* raw_scale = (const float*)d_in[0];
    const float* raw_exps  = (const float*)d_in[1];
    const float* raw_rot   = (const float*)d_in[2];
    const float* trans     = (const float*)d_in[3];
    const float* points    = (const float*)d_in[4];
    int P = in_sizes[4] / 3;

    sq_precompute<<<1, 64>>>(raw_scale, raw_exps, raw_rot, trans);

    int total_threads = (P + PPT - 1) / PPT;
    int blocks = (total_threads + TPB - 1) / TPB;
    sq_main<<<blocks, TPB>>>(points, (float*)d_out, P);
}

// round 8
// speedup vs baseline: 1.3351x; 1.1654x over previous
#include <cuda_runtime.h>

#define NSQ     64
#define TPB     128
#define EPSF    1e-6f
#define TRUNCF  0.1f

// Per-SQ params as 5 float4s (80B, 16B-aligned):
//  v0 = (M00, M01, M02, tx)
//  v1 = (M10, M11, M12, ty)
//  v2 = (M20, M21, M22, tz)
//  v3 = (isx, isy, isz, 2/e1)
//  v4 = (2/e2, e2/e1, -e1/2, 0)
__device__ float4 g_params[NSQ * 5];

__global__ void sq_precompute(const float* __restrict__ raw_scale,
                              const float* __restrict__ raw_exps,
                              const float* __restrict__ raw_rot,
                              const float* __restrict__ trans) {
    int j = threadIdx.x;
    if (j >= NSQ) return;

    float sx = expf(raw_scale[3 * j + 0]);
    float sy = expf(raw_scale[3 * j + 1]);
    float sz = expf(raw_scale[3 * j + 2]);

    float e1 = 0.1f + 1.8f / (1.0f + expf(-raw_exps[2 * j + 0]));
    float e2 = 0.1f + 1.8f / (1.0f + expf(-raw_exps[2 * j + 1]));

    float qw = raw_rot[4 * j + 0], qx = raw_rot[4 * j + 1];
    float qy = raw_rot[4 * j + 2], qz = raw_rot[4 * j + 3];
    float qn = sqrtf(qw * qw + qx * qx + qy * qy + qz * qz);
    qw /= qn; qx /= qn; qy /= qn; qz /= qn;

    float R00 = 1.f - 2.f * (qy * qy + qz * qz);
    float R01 = 2.f * (qx * qy - qw * qz);
    float R02 = 2.f * (qx * qz + qw * qy);
    float R10 = 2.f * (qx * qy + qw * qz);
    float R11 = 1.f - 2.f * (qx * qx + qz * qz);
    float R12 = 2.f * (qy * qz - qw * qx);
    float R20 = 2.f * (qx * qz - qw * qy);
    float R21 = 2.f * (qy * qz + qw * qx);
    float R22 = 1.f - 2.f * (qx * qx + qy * qy);

    float tx = trans[3 * j + 0], ty = trans[3 * j + 1], tz = trans[3 * j + 2];

    // M = R^T: row i of M = column i of R
    g_params[j * 5 + 0] = make_float4(R00, R10, R20, tx);
    g_params[j * 5 + 1] = make_float4(R01, R11, R21, ty);
    g_params[j * 5 + 2] = make_float4(R02, R12, R22, tz);
    g_params[j * 5 + 3] = make_float4(1.f / sx, 1.f / sy, 1.f / sz, 2.f / e1);
    g_params[j * 5 + 4] = make_float4(2.f / e2, e2 / e1, -0.5f * e1, 0.f);
}

__device__ __forceinline__ float powlog(float lg, float e) { return exp2f(e * lg); }

__global__ void __launch_bounds__(TPB)
sq_main(const float* __restrict__ points, float* __restrict__ out, int P) {
    __shared__ float4 sp[NSQ * 5];
    for (int i = threadIdx.x; i < NSQ * 5; i += TPB) sp[i] = g_params[i];
    __syncthreads();

    const int i = blockIdx.x * TPB + threadIdx.x;
    const int ii = (i < P) ? i : 0;
    const float px = points[3 * ii + 0];
    const float py = points[3 * ii + 1];
    const float pz = points[3 * ii + 2];

    float best = 3.0e38f;
    int bidx = 0;

    // ---- Phase 1: SDF only, first-strict-min over SQ index ----
#pragma unroll 1
    for (int j = 0; j < NSQ; j++) {
        float4 v0 = sp[j * 5 + 0];
        float4 v1 = sp[j * 5 + 1];
        float4 v2 = sp[j * 5 + 2];
        float4 v3 = sp[j * 5 + 3];
        float4 v4 = sp[j * 5 + 4];

        float ux = px - v0.w, uy = py - v1.w, uz = pz - v2.w;
        float c0 = fmaf(v0.z, uz, fmaf(v0.y, uy, v0.x * ux));
        float c1 = fmaf(v1.z, uz, fmaf(v1.y, uy, v1.x * ux));
        float c2 = fmaf(v2.z, uz, fmaf(v2.y, uy, v2.x * ux));
        float xa = fmaxf(fabsf(c0), EPSF);
        float ya = fmaxf(fabsf(c1), EPSF);
        float za = fmaxf(fabsf(c2), EPSF);
        float r0 = sqrtf(fmaf(xa, xa, fmaf(ya, ya, za * za)));
        // t1 = ((x/sx)^2)^(1/e2) = exp2((2/e2)*log2(|x|/sx))
        float t1 = powlog(__log2f(xa * v3.x), v4.x);
        float t2 = powlog(__log2f(ya * v3.y), v4.x);
        float t3 = powlog(__log2f(za * v3.z), v3.w);
        float h = t1 + t2 + EPSF;
        float hp = powlog(__log2f(h), v4.y);
        float g = hp + t3;
        float f = powlog(__log2f(g), v4.z);
        float s = r0 * (1.0f - f);
        s = fminf(fmaxf(s, -TRUNCF), TRUNCF);
        bool lt = s < best;
        best = lt ? s : best;
        bidx = lt ? j : bidx;
    }

    // ---- Phase 2: analytic gradient for the winning SQ ----
    if (i < P) {
        float4 v0 = sp[bidx * 5 + 0];
        float4 v1 = sp[bidx * 5 + 1];
        float4 v2 = sp[bidx * 5 + 2];
        float4 v3 = sp[bidx * 5 + 3];
        float4 v4 = sp[bidx * 5 + 4];

        float ux = px - v0.w, uy = py - v1.w, uz = pz - v2.w;
        float c0 = fmaf(v0.z, uz, fmaf(v0.y, uy, v0.x * ux));
        float c1 = fmaf(v1.z, uz, fmaf(v1.y, uy, v1.x * ux));
        float c2 = fmaf(v2.z, uz, fmaf(v2.y, uy, v2.x * ux));
        float xa = fmaxf(fabsf(c0), EPSF);
        float ya = fmaxf(fabsf(c1), EPSF);
        float za = fmaxf(fabsf(c2), EPSF);
        // signed clamped coords: sign = (Xc>0)*2-1 (matches reference at 0)
        float x = (c0 > 0.f) ? xa : -xa;
        float y = (c1 > 0.f) ? ya : -ya;
        float z = (c2 > 0.f) ? za : -za;
        float r0 = sqrtf(fmaf(xa, xa, fmaf(ya, ya, za * za)));
        float t1 = powlog(__log2f(xa * v3.x), v4.x);
        float t2 = powlog(__log2f(ya * v3.y), v4.x);
        float t3 = powlog(__log2f(za * v3.z), v3.w);
        float h = t1 + t2 + EPSF;
        float hp = powlog(__log2f(h), v4.y);
        float g = hp + t3;
        float f = powlog(__log2f(g), v4.z);

        float inv_r0 = 1.0f / r0;
        float omf = 1.0f - f;
        float com = r0 * (f / g);      // r0 * f / g
        float hh  = hp / h;            // h^(e2/e1 - 1)

        // d sdf / d X_i  ((e1/2) factors cancel against -e1/2 power exponent)
        // eps-clamp active -> zero gradient through max(|Xc|, eps)
        float gx = (fabsf(c0) > EPSF) ? fmaf(x * inv_r0, omf, com * hh * (t1 / x)) : 0.0f;
        float gy = (fabsf(c1) > EPSF) ? fmaf(y * inv_r0, omf, com * hh * (t2 / y)) : 0.0f;
        float gz = (fabsf(c2) > EPSF) ? fmaf(z * inv_r0, omf, com * (t3 / z)) : 0.0f;

        // back to world frame: grad_p = M^T * gX (M = R^T -> grad_p = R * gX)
        float gpx = fmaf(v2.x, gz, fmaf(v1.x, gy, v0.x * gx));
        float gpy = fmaf(v2.y, gz, fmaf(v1.y, gy, v0.y * gx));
        float gpz = fmaf(v2.z, gz, fmaf(v1.z, gy, v0.z * gx));

        float nn = sqrtf(fmaf(gpx, gpx, fmaf(gpy, gpy, gpz * gpz)));
        float dn = fmaxf(nn, 1e-12f);

        out[i] = best;
        float* on = out + P;
        on[3 * i + 0] = gpx / dn;
        on[3 * i + 1] = gpy / dn;
        on[3 * i + 2] = gpz / dn;
    }
}

extern "C" void kernel_launch(void* const* d_in, const int* in_sizes, int n_in,
                              void* d_out, int out_size) {
    const float* raw_scale = (const float*)d_in[0];
    const float* raw_exps  = (const float*)d_in[1];
    const float* raw_rot   = (const float*)d_in[2];
    const float* trans     = (const float*)d_in[3];
    const float* points    = (const float*)d_in[4];
    int P = in_sizes[4] / 3;

    sq_precompute<<<1, 64>>>(raw_scale, raw_exps, raw_rot, trans);

    int blocks = (P + TPB - 1) / TPB;
    sq_main<<<blocks, TPB>>>(points, (float*)d_out, P);
}

// round 10
// speedup vs baseline: 1.7540x; 1.3138x over previous
#include <cuda_runtime.h>

#define NSQ     64
#define TPB     128
#define EPSF    1e-6f
#define TRUNCF  0.1f

// Per-SQ params as 5 float4s (80B, 16B-aligned):
//  v0 = (M00, M01, M02, tx)
//  v1 = (M10, M11, M12, ty)
//  v2 = (M20, M21, M22, tz)
//  v3 = (isx, isy, isz, 2/e1)
//  v4 = (2/e2, e2/e1, -e1/2, 0)
__device__ float4 g_params[NSQ * 5];

__global__ void sq_precompute(const float* __restrict__ raw_scale,
                              const float* __restrict__ raw_exps,
                              const float* __restrict__ raw_rot,
                              const float* __restrict__ trans) {
    int j = threadIdx.x;
    if (j >= NSQ) return;

    float sx = expf(raw_scale[3 * j + 0]);
    float sy = expf(raw_scale[3 * j + 1]);
    float sz = expf(raw_scale[3 * j + 2]);

    float e1 = 0.1f + 1.8f / (1.0f + expf(-raw_exps[2 * j + 0]));
    float e2 = 0.1f + 1.8f / (1.0f + expf(-raw_exps[2 * j + 1]));

    float qw = raw_rot[4 * j + 0], qx = raw_rot[4 * j + 1];
    float qy = raw_rot[4 * j + 2], qz = raw_rot[4 * j + 3];
    float qn = sqrtf(qw * qw + qx * qx + qy * qy + qz * qz);
    qw /= qn; qx /= qn; qy /= qn; qz /= qn;

    float R00 = 1.f - 2.f * (qy * qy + qz * qz);
    float R01 = 2.f * (qx * qy - qw * qz);
    float R02 = 2.f * (qx * qz + qw * qy);
    float R10 = 2.f * (qx * qy + qw * qz);
    float R11 = 1.f - 2.f * (qx * qx + qz * qz);
    float R12 = 2.f * (qy * qz - qw * qx);
    float R20 = 2.f * (qx * qz - qw * qy);
    float R21 = 2.f * (qy * qz + qw * qx);
    float R22 = 1.f - 2.f * (qx * qx + qy * qy);

    float tx = trans[3 * j + 0], ty = trans[3 * j + 1], tz = trans[3 * j + 2];

    // M = R^T: row i of M = column i of R
    g_params[j * 5 + 0] = make_float4(R00, R10, R20, tx);
    g_params[j * 5 + 1] = make_float4(R01, R11, R21, ty);
    g_params[j * 5 + 2] = make_float4(R02, R12, R22, tz);
    g_params[j * 5 + 3] = make_float4(1.f / sx, 1.f / sy, 1.f / sz, 2.f / e1);
    g_params[j * 5 + 4] = make_float4(2.f / e2, e2 / e1, -0.5f * e1, 0.f);
}

// Single-instruction MUFU paths (no library range-fixup sequences).
__device__ __forceinline__ float fast_lg2(float a) {
    float r; asm("lg2.approx.ftz.f32 %0, %1;" : "=f"(r) : "f"(a)); return r;
}
__device__ __forceinline__ float fast_ex2(float a) {
    float r; asm("ex2.approx.ftz.f32 %0, %1;" : "=f"(r) : "f"(a)); return r;
}
__device__ __forceinline__ float fast_rsq(float a) {
    float r; asm("rsqrt.approx.ftz.f32 %0, %1;" : "=f"(r) : "f"(a)); return r;
}
__device__ __forceinline__ float powlog(float lg, float e) { return fast_ex2(e * lg); }

__global__ void __launch_bounds__(TPB)
sq_main(const float* __restrict__ points, float* __restrict__ out, int P) {
    __shared__ float4 sp[NSQ * 5];
    for (int i = threadIdx.x; i < NSQ * 5; i += TPB) sp[i] = g_params[i];
    __syncthreads();

    const int i = blockIdx.x * TPB + threadIdx.x;
    const int ii = (i < P) ? i : 0;
    const float px = points[3 * ii + 0];
    const float py = points[3 * ii + 1];
    const float pz = points[3 * ii + 2];

    float best = 3.0e38f;
    int bidx = 0;

    // ---- Phase 1: SDF only, first-strict-min over SQ index ----
#pragma unroll 2
    for (int j = 0; j < NSQ; j++) {
        float4 v0 = sp[j * 5 + 0];
        float4 v1 = sp[j * 5 + 1];
        float4 v2 = sp[j * 5 + 2];
        float4 v3 = sp[j * 5 + 3];
        float4 v4 = sp[j * 5 + 4];

        float ux = px - v0.w, uy = py - v1.w, uz = pz - v2.w;
        float c0 = fmaf(v0.z, uz, fmaf(v0.y, uy, v0.x * ux));
        float c1 = fmaf(v1.z, uz, fmaf(v1.y, uy, v1.x * ux));
        float c2 = fmaf(v2.z, uz, fmaf(v2.y, uy, v2.x * ux));
        float xa = fmaxf(fabsf(c0), EPSF);
        float ya = fmaxf(fabsf(c1), EPSF);
        float za = fmaxf(fabsf(c2), EPSF);
        float r2 = fmaf(xa, xa, fmaf(ya, ya, za * za));
        float r0 = r2 * fast_rsq(r2);            // sqrt(r2), 2 instrs
        // t1 = ((x/sx)^2)^(1/e2) = exp2((2/e2)*log2(|x|/sx))
        float t1 = powlog(fast_lg2(xa * v3.x), v4.x);
        float t2 = powlog(fast_lg2(ya * v3.y), v4.x);
        float t3 = powlog(fast_lg2(za * v3.z), v3.w);
        float h = t1 + t2 + EPSF;
        float hp = powlog(fast_lg2(h), v4.y);
        float g = hp + t3;
        float f = powlog(fast_lg2(g), v4.z);
        float s = r0 * (1.0f - f);
        s = fminf(fmaxf(s, -TRUNCF), TRUNCF);
        bool lt = s < best;
        best = lt ? s : best;
        bidx = lt ? j : bidx;
    }

    // ---- Phase 2: analytic gradient for the winning SQ ----
    if (i < P) {
        float4 v0 = sp[bidx * 5 + 0];
        float4 v1 = sp[bidx * 5 + 1];
        float4 v2 = sp[bidx * 5 + 2];
        float4 v3 = sp[bidx * 5 + 3];
        float4 v4 = sp[bidx * 5 + 4];

        float ux = px - v0.w, uy = py - v1.w, uz = pz - v2.w;
        float c0 = fmaf(v0.z, uz, fmaf(v0.y, uy, v0.x * ux));
        float c1 = fmaf(v1.z, uz, fmaf(v1.y, uy, v1.x * ux));
        float c2 = fmaf(v2.z, uz, fmaf(v2.y, uy, v2.x * ux));
        float xa = fmaxf(fabsf(c0), EPSF);
        float ya = fmaxf(fabsf(c1), EPSF);
        float za = fmaxf(fabsf(c2), EPSF);
        // signed clamped coords: sign = (Xc>0)*2-1 (matches reference at 0)
        float x = (c0 > 0.f) ? xa : -xa;
        float y = (c1 > 0.f) ? ya : -ya;
        float z = (c2 > 0.f) ? za : -za;
        float r2 = fmaf(xa, xa, fmaf(ya, ya, za * za));
        float inv_r0 = fast_rsq(r2);
        float r0 = r2 * inv_r0;
        float t1 = powlog(fast_lg2(xa * v3.x), v4.x);
        float t2 = powlog(fast_lg2(ya * v3.y), v4.x);
        float t3 = powlog(fast_lg2(za * v3.z), v3.w);
        float h = t1 + t2 + EPSF;
        float hp = powlog(fast_lg2(h), v4.y);
        float g = hp + t3;
        float f = powlog(fast_lg2(g), v4.z);

        float omf = 1.0f - f;
        float com = r0 * (f / g);      // r0 * f / g
        float hh  = hp / h;            // h^(e2/e1 - 1)

        // d sdf / d X_i  ((e1/2) factors cancel against -e1/2 power exponent)
        // eps-clamp active -> zero gradient through max(|Xc|, eps)
        float gx = (fabsf(c0) > EPSF) ? fmaf(x * inv_r0, omf, com * hh * (t1 / x)) : 0.0f;
        float gy = (fabsf(c1) > EPSF) ? fmaf(y * inv_r0, omf, com * hh * (t2 / y)) : 0.0f;
        float gz = (fabsf(c2) > EPSF) ? fmaf(z * inv_r0, omf, com * (t3 / z)) : 0.0f;

        // back to world frame: grad_p = M^T * gX (M = R^T -> grad_p = R * gX)
        float gpx = fmaf(v2.x, gz, fmaf(v1.x, gy, v0.x * gx));
        float gpy = fmaf(v2.y, gz, fmaf(v1.y, gy, v0.y * gx));
        float gpz = fmaf(v2.z, gz, fmaf(v1.z, gy, v0.z * gx));

        float nn2 = fmaf(gpx, gpx, fmaf(gpy, gpy, gpz * gpz));
        // normalize: grad / max(|grad|, 1e-12). |grad| >= ~1e-12 handled via rsqrt;
        // if grad == 0 exactly (all eps-clamped), output zeros like the reference.
        float inn = (nn2 > 1e-24f) ? fast_rsq(nn2) : 0.0f;

        out[i] = best;
        float* on = out + P;
        on[3 * i + 0] = gpx * inn;
        on[3 * i + 1] = gpy * inn;
        on[3 * i + 2] = gpz * inn;
    }
}

extern "C" void kernel_launch(void* const* d_in, const int* in_sizes, int n_in,
                              void* d_out, int out_size) {
    const float* raw_scale = (const float*)d_in[0];
    const float* raw_exps  = (const float*)d_in[1];
    const float* raw_rot   = (const float*)d_in[2];
    const float* trans     = (const float*)d_in[3];
    const float* points    = (const float*)d_in[4];
    int P = in_sizes[4] / 3;

    sq_precompute<<<1, 64>>>(raw_scale, raw_exps, raw_rot, trans);

    int blocks = (P + TPB - 1) / TPB;
    sq_main<<<blocks, TPB>>>(points, (float*)d_out, P);
}

// round 15
// speedup vs baseline: 1.7701x; 1.0092x over previous
#include <cuda_runtime.h>

#define NSQ     64
#define TPB     128
#define EPSF    1e-6f
#define TRUNCF  0.1f

// Per-SQ params, 6 float4s (96B):
//  v0 = (M00, M01, M02, tx)   M = R^T, Xc = M (p - t)
//  v1 = (M10, M11, M12, ty)
//  v2 = (M20, M21, M22, tz)
//  v3 = (ie2, ie1, e21, nh1)  = (2/e2, 2/e1, e2/e1, -e1/2)
//  v4 = (Cpx, Cpy, Cbz, 0)    = (ie2*lg2(isx), ie2*lg2(isy), ie1*lg2(isz), 0)
//  v5 = (isx, isy, isz, 0)    (phase 2 only)
__device__ float4 g_params[NSQ * 6];

__global__ void sq_precompute(const float* __restrict__ raw_scale,
                              const float* __restrict__ raw_exps,
                              const float* __restrict__ raw_rot,
                              const float* __restrict__ trans) {
    int j = threadIdx.x;
    if (j >= NSQ) return;

    float sx = expf(raw_scale[3 * j + 0]);
    float sy = expf(raw_scale[3 * j + 1]);
    float sz = expf(raw_scale[3 * j + 2]);

    float e1 = 0.1f + 1.8f / (1.0f + expf(-raw_exps[2 * j + 0]));
    float e2 = 0.1f + 1.8f / (1.0f + expf(-raw_exps[2 * j + 1]));

    float qw = raw_rot[4 * j + 0], qx = raw_rot[4 * j + 1];
    float qy = raw_rot[4 * j + 2], qz = raw_rot[4 * j + 3];
    float qn = sqrtf(qw * qw + qx * qx + qy * qy + qz * qz);
    qw /= qn; qx /= qn; qy /= qn; qz /= qn;

    float R00 = 1.f - 2.f * (qy * qy + qz * qz);
    float R01 = 2.f * (qx * qy - qw * qz);
    float R02 = 2.f * (qx * qz + qw * qy);
    float R10 = 2.f * (qx * qy + qw * qz);
    float R11 = 1.f - 2.f * (qx * qx + qz * qz);
    float R12 = 2.f * (qy * qz - qw * qx);
    float R20 = 2.f * (qx * qz - qw * qy);
    float R21 = 2.f * (qy * qz + qw * qx);
    float R22 = 1.f - 2.f * (qx * qx + qy * qy);

    float tx = trans[3 * j + 0], ty = trans[3 * j + 1], tz = trans[3 * j + 2];

    float isx = 1.f / sx, isy = 1.f / sy, isz = 1.f / sz;
    float ie1 = 2.f / e1, ie2 = 2.f / e2;

    g_params[j * 6 + 0] = make_float4(R00, R10, R20, tx);
    g_params[j * 6 + 1] = make_float4(R01, R11, R21, ty);
    g_params[j * 6 + 2] = make_float4(R02, R12, R22, tz);
    g_params[j * 6 + 3] = make_float4(ie2, ie1, e2 / e1, -0.5f * e1);
    g_params[j * 6 + 4] = make_float4(ie2 * log2f(isx), ie2 * log2f(isy),
                                      ie1 * log2f(isz), 0.f);
    g_params[j * 6 + 5] = make_float4(isx, isy, isz, 0.f);
}

// Single-instruction MUFU paths.
__device__ __forceinline__ float fast_lg2(float a) {
    float r; asm("lg2.approx.ftz.f32 %0, %1;" : "=f"(r) : "f"(a)); return r;
}
__device__ __forceinline__ float fast_ex2(float a) {
    float r; asm("ex2.approx.ftz.f32 %0, %1;" : "=f"(r) : "f"(a)); return r;
}
__device__ __forceinline__ float fast_rsq(float a) {
    float r; asm("rsqrt.approx.ftz.f32 %0, %1;" : "=f"(r) : "f"(a)); return r;
}
__device__ __forceinline__ float powlog(float lg, float e) { return fast_ex2(e * lg); }

// lg2(1+u) on u in [0,1]: Taylor of ln(1.5+(u-0.5)) about u=0.5, deg 10.
// Max abs err ~1.1e-6 (checked at u=0 and u=1). Pure FMA, no MUFU.
__device__ __forceinline__ float lg2_1p(float u) {
    const float c0  =  0.5849625007f;   // log2(1.5)
    const float c1  =  0.9617966939f;
    const float c2  = -0.3205988980f;
    const float c3  =  0.1424883991f;
    const float c4  = -0.0712441996f;
    const float c5  =  0.0379969064f;
    const float c6  = -0.0211093920f;
    const float c7  =  0.0120628420f;
    const float c8  = -0.0070364912f;
    const float c9  =  0.0041697000f;
    const float c10 = -0.0025019000f;
    float w = u - 0.5f;
    float acc = c10;
    acc = fmaf(acc, w, c9);
    acc = fmaf(acc, w, c8);
    acc = fmaf(acc, w, c7);
    acc = fmaf(acc, w, c6);
    acc = fmaf(acc, w, c5);
    acc = fmaf(acc, w, c4);
    acc = fmaf(acc, w, c3);
    acc = fmaf(acc, w, c2);
    acc = fmaf(acc, w, c1);
    return fmaf(acc, w, c0);
}

__global__ void __launch_bounds__(TPB)
sq_main(const float* __restrict__ points, float* __restrict__ out, int P) {
    __shared__ float4 sp[NSQ * 6];
    for (int i = threadIdx.x; i < NSQ * 6; i += TPB) sp[i] = g_params[i];
    __syncthreads();

    const int i = blockIdx.x * TPB + threadIdx.x;
    const int ii = (i < P) ? i : 0;
    const float px = points[3 * ii + 0];
    const float py = points[3 * ii + 1];
    const float pz = points[3 * ii + 2];

    float best = 3.0e38f;
    int bidx = 0;

    // ---- Phase 1: SDF only, first-strict-min over SQ index (9 MUFU/eval) ----
#pragma unroll 2
    for (int j = 0; j < NSQ; j++) {
        float4 v0 = sp[j * 6 + 0];
        float4 v1 = sp[j * 6 + 1];
        float4 v2 = sp[j * 6 + 2];
        float4 v3 = sp[j * 6 + 3];
        float4 v4 = sp[j * 6 + 4];

        float ux = px - v0.w, uy = py - v1.w, uz = pz - v2.w;
        float c0 = fmaf(v0.z, uz, fmaf(v0.y, uy, v0.x * ux));
        float c1 = fmaf(v1.z, uz, fmaf(v1.y, uy, v1.x * ux));
        float c2 = fmaf(v2.z, uz, fmaf(v2.y, uy, v2.x * ux));
        float xa = fmaxf(fabsf(c0), EPSF);
        float ya = fmaxf(fabsf(c1), EPSF);
        float za = fmaxf(fabsf(c2), EPSF);
        float r2 = fmaf(xa, xa, fmaf(ya, ya, za * za));
        float r0 = r2 * fast_rsq(r2);                 // sqrt(r2)

        // log-domain exponents: p = lg2(t1), q = lg2(t2), b = lg2(t3)
        float p = fmaf(v3.x, fast_lg2(xa), v4.x);
        float q = fmaf(v3.x, fast_lg2(ya), v4.y);
        float b = fmaf(v3.y, fast_lg2(za), v4.z);

        float t1 = fast_ex2(p);
        float t2 = fast_ex2(q);
        float h = t1 + t2 + EPSF;
        float a = v3.z * fast_lg2(h);                 // lg2(hp) = (e2/e1)*lg2(h)

        // lg2(g) = lg2(2^a + 2^b) = max + lg2(1 + 2^-(|a-b|))  [LSE, no overflow]
        float m2 = fmaxf(a, b);
        float u  = fast_ex2(fminf(a, b) - m2);        // in (0, 1]
        float Lg = m2 + lg2_1p(u);

        float f = fast_ex2(v3.w * Lg);                // g^(-e1/2)
        float s = r0 * (1.0f - f);
        s = fminf(fmaxf(s, -TRUNCF), TRUNCF);
        bool lt = s < best;
        best = lt ? s : best;
        bidx = lt ? j : bidx;
    }

    // ---- Phase 2: analytic gradient for the winning SQ (once per point) ----
    if (i < P) {
        float4 v0 = sp[bidx * 6 + 0];
        float4 v1 = sp[bidx * 6 + 1];
        float4 v2 = sp[bidx * 6 + 2];
        float4 v3 = sp[bidx * 6 + 3];
        float4 v5 = sp[bidx * 6 + 5];

        float ie2 = v3.x, ie1 = v3.y, e21 = v3.z, nh1 = v3.w;

        float ux = px - v0.w, uy = py - v1.w, uz = pz - v2.w;
        float c0 = fmaf(v0.z, uz, fmaf(v0.y, uy, v0.x * ux));
        float c1 = fmaf(v1.z, uz, fmaf(v1.y, uy, v1.x * ux));
        float c2 = fmaf(v2.z, uz, fmaf(v2.y, uy, v2.x * ux));
        float xa = fmaxf(fabsf(c0), EPSF);
        float ya = fmaxf(fabsf(c1), EPSF);
        float za = fmaxf(fabsf(c2), EPSF);
        // signed clamped coords: sign = (Xc>0)*2-1 (matches reference at 0)
        float x = (c0 > 0.f) ? xa : -xa;
        float y = (c1 > 0.f) ? ya : -ya;
        float z = (c2 > 0.f) ? za : -za;
        float r2 = fmaf(xa, xa, fmaf(ya, ya, za * za));
        float inv_r0 = fast_rsq(r2);
        float r0 = r2 * inv_r0;
        float t1 = powlog(fast_lg2(xa * v5.x), ie2);
        float t2 = powlog(fast_lg2(ya * v5.y), ie2);
        float t3 = powlog(fast_lg2(za * v5.z), ie1);
        float h = t1 + t2 + EPSF;
        float lgh = fast_lg2(h);
        // LSE form for g too (avoids hp = inf overflow)
        float aa = e21 * lgh;
        float bb = fast_lg2(t3);
        float m2 = fmaxf(aa, bb);
        float uu = fast_ex2(fminf(aa, bb) - m2);
        float Lg = m2 + lg2_1p(uu);
        float f  = fast_ex2(nh1 * Lg);

        float omf = 1.0f - f;
        // com = r0 * f / g; f/g = 2^(nh1*Lg - Lg) = 2^((nh1-1)*Lg)
        float com = r0 * fast_ex2((nh1 - 1.0f) * Lg);
        // hh = hp/h = 2^(e21*lgh - lgh)
        float hh = fast_ex2((e21 - 1.0f) * lgh);

        // d sdf / d X_i  ((e1/2) factors cancel against -e1/2 power exponent)
        // eps-clamp active -> zero gradient through max(|Xc|, eps)
        float gx = (fabsf(c0) > EPSF) ? fmaf(x * inv_r0, omf, com * hh * (t1 / x)) : 0.0f;
        float gy = (fabsf(c1) > EPSF) ? fmaf(y * inv_r0, omf, com * hh * (t2 / y)) : 0.0f;
        float gz = (fabsf(c2) > EPSF) ? fmaf(z * inv_r0, omf, com * (t3 / z)) : 0.0f;

        // back to world frame: grad_p = M^T * gX (M = R^T -> grad_p = R * gX)
        float gpx = fmaf(v2.x, gz, fmaf(v1.x, gy, v0.x * gx));
        float gpy = fmaf(v2.y, gz, fmaf(v1.y, gy, v0.y * gx));
        float gpz = fmaf(v2.z, gz, fmaf(v1.z, gy, v0.z * gx));

        float nn2 = fmaf(gpx, gpx, fmaf(gpy, gpy, gpz * gpz));
        // normalize: grad / max(|grad|, 1e-12); exact-zero grad -> zeros
        float inn = (nn2 > 1e-24f) ? fast_rsq(nn2) : 0.0f;

        out[i] = best;
        float* on = out + P;
        on[3 * i + 0] = gpx * inn;
        on[3 * i + 1] = gpy * inn;
        on[3 * i + 2] = gpz * inn;
    }
}

extern "C" void kernel_launch(void* const* d_in, const int* in_sizes, int n_in,
                              void* d_out, int out_size) {
    const float* raw_scale = (const float*)d_in[0];
    const float* raw_exps  = (const float*)d_in[1];
    const float* raw_rot   = (const float*)d_in[2];
    const float* trans     = (const float*)d_in[3];
    const float* points    = (const float*)d_in[4];
    int P = in_sizes[4] / 3;

    sq_precompute<<<1, 64>>>(raw_scale, raw_exps, raw_rot, trans);

    int blocks = (P + TPB - 1) / TPB;
    sq_main<<<blocks, TPB>>>(points, (float*)d_out, P);
}

// round 17
// speedup vs baseline: 1.8361x; 1.0373x over previous
#include <cuda_runtime.h>

#define NSQ     64
#define TPB     128
#define EPSF    1e-6f
#define TRUNCF  0.1f

// Per-SQ params, 6 float4s (96B):
//  v0 = (M00, M01, M02, tx)   M = R^T, Xc = M (p - t)
//  v1 = (M10, M11, M12, ty)
//  v2 = (M20, M21, M22, tz)
//  v3 = (ie2, ie1, e21, nh1)  = (2/e2, 2/e1, e2/e1, -e1/2)
//  v4 = (Cpx, Cpy, Cbz, 0)    = (ie2*lg2(isx), ie2*lg2(isy), ie1*lg2(isz), 0)
//  v5 = (isx, isy, isz, 0)    (phase 2 only)
__device__ float4 g_params[NSQ * 6];

__global__ void sq_precompute(const float* __restrict__ raw_scale,
                              const float* __restrict__ raw_exps,
                              const float* __restrict__ raw_rot,
                              const float* __restrict__ trans) {
    int j = threadIdx.x;
    if (j >= NSQ) return;

    float sx = expf(raw_scale[3 * j + 0]);
    float sy = expf(raw_scale[3 * j + 1]);
    float sz = expf(raw_scale[3 * j + 2]);

    float e1 = 0.1f + 1.8f / (1.0f + expf(-raw_exps[2 * j + 0]));
    float e2 = 0.1f + 1.8f / (1.0f + expf(-raw_exps[2 * j + 1]));

    float qw = raw_rot[4 * j + 0], qx = raw_rot[4 * j + 1];
    float qy = raw_rot[4 * j + 2], qz = raw_rot[4 * j + 3];
    float qn = sqrtf(qw * qw + qx * qx + qy * qy + qz * qz);
    qw /= qn; qx /= qn; qy /= qn; qz /= qn;

    float R00 = 1.f - 2.f * (qy * qy + qz * qz);
    float R01 = 2.f * (qx * qy - qw * qz);
    float R02 = 2.f * (qx * qz + qw * qy);
    float R10 = 2.f * (qx * qy + qw * qz);
    float R11 = 1.f - 2.f * (qx * qx + qz * qz);
    float R12 = 2.f * (qy * qz - qw * qx);
    float R20 = 2.f * (qx * qz - qw * qy);
    float R21 = 2.f * (qy * qz + qw * qx);
    float R22 = 1.f - 2.f * (qx * qx + qy * qy);

    float tx = trans[3 * j + 0], ty = trans[3 * j + 1], tz = trans[3 * j + 2];

    float isx = 1.f / sx, isy = 1.f / sy, isz = 1.f / sz;
    float ie1 = 2.f / e1, ie2 = 2.f / e2;

    g_params[j * 6 + 0] = make_float4(R00, R10, R20, tx);
    g_params[j * 6 + 1] = make_float4(R01, R11, R21, ty);
    g_params[j * 6 + 2] = make_float4(R02, R12, R22, tz);
    g_params[j * 6 + 3] = make_float4(ie2, ie1, e2 / e1, -0.5f * e1);
    g_params[j * 6 + 4] = make_float4(ie2 * log2f(isx), ie2 * log2f(isy),
                                      ie1 * log2f(isz), 0.f);
    g_params[j * 6 + 5] = make_float4(isx, isy, isz, 0.f);
}

// Single-instruction MUFU paths.
__device__ __forceinline__ float fast_lg2(float a) {
    float r; asm("lg2.approx.ftz.f32 %0, %1;" : "=f"(r) : "f"(a)); return r;
}
__device__ __forceinline__ float fast_ex2(float a) {
    float r; asm("ex2.approx.ftz.f32 %0, %1;" : "=f"(r) : "f"(a)); return r;
}
__device__ __forceinline__ float fast_rsq(float a) {
    float r; asm("rsqrt.approx.ftz.f32 %0, %1;" : "=f"(r) : "f"(a)); return r;
}
__device__ __forceinline__ float powlog(float lg, float e) { return fast_ex2(e * lg); }

// lg2(1+u), u in [0,1]: degree-6 Chebyshev of ln(1.5+w) about w=0 mapped to
// t = 2u-1 in [-1,1] (z = 0.17157, truncation err 2 z^7/7 / ln2 ~ 1.9e-6 abs;
// endpoint-checked: u=0 -> +1.5e-6, u=1 -> exact). 7 FMA, no MUFU.
__device__ __forceinline__ float lg2_1p(float u) {
    const float d6 = -0.0003926f;
    const float d5 =  0.0013729f;
    const float d4 = -0.0044118f;
    const float d3 =  0.0177147f;
    const float d2 = -0.0801580f;
    const float d1 =  0.48091065f;
    const float d0 =  0.58496217f;   // log2(1.5) + tiny Chebyshev shift
    float t = fmaf(2.0f, u, -1.0f);
    float acc = d6;
    acc = fmaf(acc, t, d5);
    acc = fmaf(acc, t, d4);
    acc = fmaf(acc, t, d3);
    acc = fmaf(acc, t, d2);
    acc = fmaf(acc, t, d1);
    return fmaf(acc, t, d0);
}

__global__ void __launch_bounds__(TPB, 8)
sq_main(const float* __restrict__ points, float* __restrict__ out, int P) {
    __shared__ float4 sp[NSQ * 6];
    for (int i = threadIdx.x; i < NSQ * 6; i += TPB) sp[i] = g_params[i];
    __syncthreads();

    const int i = blockIdx.x * TPB + threadIdx.x;
    const int ii = (i < P) ? i : 0;
    const float px = points[3 * ii + 0];
    const float py = points[3 * ii + 1];
    const float pz = points[3 * ii + 2];

    float best = 3.0e38f;
    int bidx = 0;

    // ---- Phase 1: SDF only, first-strict-min over SQ index (9 MUFU/eval) ----
#pragma unroll 4
    for (int j = 0; j < NSQ; j++) {
        float4 v0 = sp[j * 6 + 0];
        float4 v1 = sp[j * 6 + 1];
        float4 v2 = sp[j * 6 + 2];
        float4 v3 = sp[j * 6 + 3];
        float4 v4 = sp[j * 6 + 4];

        float ux = px - v0.w, uy = py - v1.w, uz = pz - v2.w;
        float c0 = fmaf(v0.z, uz, fmaf(v0.y, uy, v0.x * ux));
        float c1 = fmaf(v1.z, uz, fmaf(v1.y, uy, v1.x * ux));
        float c2 = fmaf(v2.z, uz, fmaf(v2.y, uy, v2.x * ux));
        float xa = fmaxf(fabsf(c0), EPSF);
        float ya = fmaxf(fabsf(c1), EPSF);
        float za = fmaxf(fabsf(c2), EPSF);
        float r2 = fmaf(xa, xa, fmaf(ya, ya, za * za));
        float r0 = r2 * fast_rsq(r2);                 // sqrt(r2)

        // log-domain exponents: p = lg2(t1), q = lg2(t2), b = lg2(t3)
        float p = fmaf(v3.x, fast_lg2(xa), v4.x);
        float q = fmaf(v3.x, fast_lg2(ya), v4.y);
        float b = fmaf(v3.y, fast_lg2(za), v4.z);

        float t1 = fast_ex2(p);
        float t2 = fast_ex2(q);
        float h = t1 + t2 + EPSF;
        float a = v3.z * fast_lg2(h);                 // lg2(hp) = (e2/e1)*lg2(h)

        // lg2(g) = lg2(2^a + 2^b) = max + lg2(1 + 2^-(|a-b|))  [LSE, no overflow]
        float m2 = fmaxf(a, b);
        float u  = fast_ex2(fminf(a, b) - m2);        // in (0, 1]
        float Lg = m2 + lg2_1p(u);

        float f = fast_ex2(v3.w * Lg);                // g^(-e1/2)
        float s = r0 * (1.0f - f);
        s = fminf(fmaxf(s, -TRUNCF), TRUNCF);
        bool lt = s < best;
        best = lt ? s : best;
        bidx = lt ? j : bidx;
    }

    // ---- Phase 2: analytic gradient for the winning SQ (once per point) ----
    if (i < P) {
        float4 v0 = sp[bidx * 6 + 0];
        float4 v1 = sp[bidx * 6 + 1];
        float4 v2 = sp[bidx * 6 + 2];
        float4 v3 = sp[bidx * 6 + 3];
        float4 v5 = sp[bidx * 6 + 5];

        float ie2 = v3.x, ie1 = v3.y, e21 = v3.z, nh1 = v3.w;

        float ux = px - v0.w, uy = py - v1.w, uz = pz - v2.w;
        float c0 = fmaf(v0.z, uz, fmaf(v0.y, uy, v0.x * ux));
        float c1 = fmaf(v1.z, uz, fmaf(v1.y, uy, v1.x * ux));
        float c2 = fmaf(v2.z, uz, fmaf(v2.y, uy, v2.x * ux));
        float xa = fmaxf(fabsf(c0), EPSF);
        float ya = fmaxf(fabsf(c1), EPSF);
        float za = fmaxf(fabsf(c2), EPSF);
        // signed clamped coords: sign = (Xc>0)*2-1 (matches reference at 0)
        float x = (c0 > 0.f) ? xa : -xa;
        float y = (c1 > 0.f) ? ya : -ya;
        float z = (c2 > 0.f) ? za : -za;
        float r2 = fmaf(xa, xa, fmaf(ya, ya, za * za));
        float inv_r0 = fast_rsq(r2);
        float r0 = r2 * inv_r0;
        float t1 = powlog(fast_lg2(xa * v5.x), ie2);
        float t2 = powlog(fast_lg2(ya * v5.y), ie2);
        float t3 = powlog(fast_lg2(za * v5.z), ie1);
        float h = t1 + t2 + EPSF;
        float lgh = fast_lg2(h);
        // LSE form for g too (avoids hp = inf overflow)
        float aa = e21 * lgh;
        float bb = fast_lg2(t3);
        float m2 = fmaxf(aa, bb);
        float uu = fast_ex2(fminf(aa, bb) - m2);
        float Lg = m2 + lg2_1p(uu);
        float f  = fast_ex2(nh1 * Lg);

        float omf = 1.0f - f;
        // com = r0 * f / g; f/g = 2^((nh1-1)*Lg)
        float com = r0 * fast_ex2((nh1 - 1.0f) * Lg);
        // hh = hp/h = 2^((e21-1)*lgh)
        float hh = fast_ex2((e21 - 1.0f) * lgh);

        // d sdf / d X_i  ((e1/2) factors cancel against -e1/2 power exponent)
        // eps-clamp active -> zero gradient through max(|Xc|, eps)
        float gx = (fabsf(c0) > EPSF) ? fmaf(x * inv_r0, omf, com * hh * (t1 / x)) : 0.0f;
        float gy = (fabsf(c1) > EPSF) ? fmaf(y * inv_r0, omf, com * hh * (t2 / y)) : 0.0f;
        float gz = (fabsf(c2) > EPSF) ? fmaf(z * inv_r0, omf, com * (t3 / z)) : 0.0f;

        // back to world frame: grad_p = M^T * gX (M = R^T -> grad_p = R * gX)
        float gpx = fmaf(v2.x, gz, fmaf(v1.x, gy, v0.x * gx));
        float gpy = fmaf(v2.y, gz, fmaf(v1.y, gy, v0.y * gx));
        float gpz = fmaf(v2.z, gz, fmaf(v1.z, gy, v0.z * gx));

        float nn2 = fmaf(gpx, gpx, fmaf(gpy, gpy, gpz * gpz));
        // normalize: grad / max(|grad|, 1e-12); exact-zero grad -> zeros
        float inn = (nn2 > 1e-24f) ? fast_rsq(nn2) : 0.0f;

        out[i] = best;
        float* on = out + P;
        on[3 * i + 0] = gpx * inn;
        on[3 * i + 1] = gpy * inn;
        on[3 * i + 2] = gpz * inn;
    }
}

extern "C" void kernel_launch(void* const* d_in, const int* in_sizes, int n_in,
                              void* d_out, int out_size) {
    const float* raw_scale = (const float*)d_in[0];
    const float* raw_exps  = (const float*)d_in[1];
    const float* raw_rot   = (const float*)d_in[2];
    const float* trans     = (const float*)d_in[3];
    const float* points    = (const float*)d_in[4];
    int P = in_sizes[4] / 3;

    sq_precompute<<<1, 64>>>(raw_scale, raw_exps, raw_rot, trans);

    int blocks = (P + TPB - 1) / TPB;
    sq_main<<<blocks, TPB>>>(points, (float*)d_out, P);
}